// round 12
// baseline (speedup 1.0000x reference)
#include <cuda_runtime.h>
#include <math.h>

#define DIM 512
#define MARGIN 1.0f
#define RULE_WEIGHT 0.5f

#define MAX_B   1024

// Scratch (allocation-free): g_dposm doubles as flag+value (0 = not ready,
// MARGIN + d >= 1 when published). Zero-init at load; reset by last block
// each call so graph replays are deterministic.
__device__ float g_dposm[MAX_B];
__device__ float g_loss = 0.f;
__device__ float g_rule_sum = 0.f;
__device__ unsigned int g_ticket = 0;

__device__ __forceinline__ float warp_red(float v) {
#pragma unroll
    for (int o = 16; o; o >>= 1) v += __shfl_xor_sync(0xffffffffu, v, o);
    return v;
}

// acq_rel ticket (validated R10): release orders this thread's prior global
// ops before the increment; winner's acquire orders subsequent loads.
// No membar.gl => no CCTL.IVALL L1-flush storm.
__device__ __forceinline__ unsigned int ticket_acq_rel(unsigned int* p) {
    unsigned int old;
    asm volatile("atom.acq_rel.gpu.global.add.u32 %0, [%1], 1;"
                 : "=r"(old) : "l"(p) : "memory");
    return old;
}

// TransH distance via expanded norm — single streaming pass over w and re,
// only hd[4] + 4 scalar accumulators register-resident (R11, measured win).
//   u = hd + re;  ||u - c*w||^2 = uu - 2c*uw + c^2*ww,  c = (hd.w)/ww
__device__ __forceinline__ float dist_lowreg(
    const float4 hd[4],
    const float* __restrict__ rel, const float* __restrict__ nv,
    int r, int lane)
{
    const float4* w4  = reinterpret_cast<const float4*>(nv  + (size_t)r * DIM);
    const float4* re4 = reinterpret_cast<const float4*>(rel + (size_t)r * DIM);
    float ww = 0.f, dw = 0.f, uu = 0.f, uw = 0.f;
#pragma unroll
    for (int i = 0; i < 4; i++) {
        float4 w  = w4[lane + 32 * i];
        float4 re = re4[lane + 32 * i];
        float ux = hd[i].x + re.x, uy = hd[i].y + re.y;
        float uz = hd[i].z + re.z, uq = hd[i].w + re.w;
        ww += w.x * w.x + w.y * w.y + w.z * w.z + w.w * w.w;
        dw += hd[i].x * w.x + hd[i].y * w.y + hd[i].z * w.z + hd[i].w * w.w;
        uu += ux * ux + uy * uy + uz * uz + uq * uq;
        uw += ux * w.x + uy * w.y + uz * w.z + uq * w.w;
    }
    ww = warp_red(ww);
    dw = warp_red(dw);
    uu = warp_red(uu);
    uw = warp_red(uw);
    float c = dw / ww;
    float ss = uu - 2.f * c * uw + c * c * ww;
    return sqrtf(fmaxf(ss, 0.f));
}

// One kernel: pos warps (gw < B, blocks 0..127 -> wave-1 resident) publish
// MARGIN+d via a single volatile 32-bit store; neg warps compute their own
// distance then spin-read the paired word (flag==value, no fence), fold relu
// into a block accumulator. Acq_rel-ticketed last block writes the scalar.
__global__ void __launch_bounds__(256)
fused_all(const int* __restrict__ pos, const int* __restrict__ neg,
          const int* __restrict__ rr1, const int* __restrict__ rr2,
          const float* __restrict__ rconf,
          const float* __restrict__ ent, const float* __restrict__ rel,
          const float* __restrict__ nv,
          float* __restrict__ out,
          int B, int NEG, int NR)
{
    int tid  = threadIdx.x;
    int gw   = (blockIdx.x * blockDim.x + tid) >> 5;
    int lane = tid & 31;

    __shared__ float s_loss;
    if (tid == 0) s_loss = 0.f;
    __syncthreads();

    if (gw < B + NEG) {
        int h, r, t;
        bool is_pos = (gw < B);
        int kneg = gw - B;
        if (is_pos) {
            h = pos[3 * gw]; r = pos[3 * gw + 1]; t = pos[3 * gw + 2];
        } else {
            h = neg[3 * kneg]; r = neg[3 * kneg + 1]; t = neg[3 * kneg + 2];
        }

        const float4* he4 = reinterpret_cast<const float4*>(ent + (size_t)h * DIM);
        const float4* te4 = reinterpret_cast<const float4*>(ent + (size_t)t * DIM);
        float4 hd[4];
#pragma unroll
        for (int i = 0; i < 4; i++) {
            float4 a = he4[lane + 32 * i];
            float4 b = te4[lane + 32 * i];
            hd[i].x = a.x - b.x; hd[i].y = a.y - b.y;
            hd[i].z = a.z - b.z; hd[i].w = a.w - b.w;
        }

        float d = dist_lowreg(hd, rel, nv, r, lane);

        if (is_pos) {
            // Only rules with rule_r1[j] == r contribute (mask exact-zeros rest).
            float racc = 0.f;
            for (int j = 0; j < NR; j++) {
                if (rr1[j] == r)
                    racc += rconf[j] * dist_lowreg(hd, rel, nv, rr2[j], lane);
            }
            if (lane == 0) {
                *(volatile float*)&g_dposm[gw] = MARGIN + d;   // publish (>=1)
                if (racc != 0.f) atomicAdd(&g_rule_sum, racc); // ~40 warps
            }
        } else {
            int kp = kneg / (NEG / B);     // paired pos index
            // Spin until published. Single word = flag AND value; volatile
            // bypasses L1. Whole warp reads same addr (broadcast).
            float pm;
            do {
                pm = *(volatile float*)&g_dposm[kp];
                if (pm != 0.f) break;
                __nanosleep(32);
            } while (true);
            float v = pm - d;              // MARGIN + d_pos - d_neg
            if (lane == 0 && v > 0.f) atomicAdd(&s_loss, v);
        }
    }

    // Block accumulate -> one global atomic per block.
    __syncthreads();
    __shared__ unsigned int s_last;
    if (tid == 0) {
        if (s_loss != 0.f) atomicAdd(&g_loss, s_loss);
        s_last = (ticket_acq_rel(&g_ticket) == gridDim.x - 1) ? 1u : 0u;
    }
    __syncthreads();
    if (!s_last) return;

    // Trivial tail: scalar combine + state reset (all blocks done => safe).
    for (int i = tid; i < B; i += blockDim.x) g_dposm[i] = 0.f;
    if (tid == 0) {
        float bl = __ldcg(&g_loss);
        float rs = __ldcg(&g_rule_sum);
        out[0] = bl / (float)NEG + RULE_WEIGHT * rs;
        g_loss = 0.f;
        g_rule_sum = 0.f;
        g_ticket = 0;
    }
}

extern "C" void kernel_launch(void* const* d_in, const int* in_sizes, int n_in,
                              void* d_out, int out_size)
{
    const int*   pos   = (const int*)d_in[0];
    const int*   neg   = (const int*)d_in[1];
    const int*   rr1   = (const int*)d_in[2];
    const int*   rr2   = (const int*)d_in[3];
    const float* rconf = (const float*)d_in[4];
    const float* ent   = (const float*)d_in[5];
    const float* rel   = (const float*)d_in[6];
    const float* nv    = (const float*)d_in[7];

    int B   = in_sizes[0] / 3;
    int NEG = in_sizes[1] / 3;
    int NR  = in_sizes[2];

    int totalWarps = B + NEG;
    int blocks = (totalWarps * 32 + 255) / 256;

    fused_all<<<blocks, 256>>>(pos, neg, rr1, rr2, rconf, ent, rel, nv,
                               (float*)d_out, B, NEG, NR);
}